// round 11
// baseline (speedup 1.0000x reference)
#include <cuda_runtime.h>
#include <math.h>
#include <float.h>

// ---------------------------------------------------------------------------
// Problem constants
// ---------------------------------------------------------------------------
#define BATCH   32
#define HW      56
#define DIM     384
#define NH      12
#define HD      32
#define WS      7
#define L       49          // tokens per window
#define NWIN    64          // windows per image (8x8)
#define BW      (BATCH*NWIN)        // 2048 windows total
#define TOK     (BATCH*HW*HW)       // 100352 tokens
#define SCALE_F 0.17677669529663687f  // HD^-0.5

typedef unsigned long long u64;

// ---------------------------------------------------------------------------
// Packed fp32x2 ops (sm_100+; confirmed accepted by ptxas at sm_103).
// Per-half round-to-nearest — numerically identical to scalar sequence.
// ---------------------------------------------------------------------------
__device__ __forceinline__ void ffma2(u64 &d, u64 a, u64 b) {
    asm("fma.rn.f32x2 %0, %1, %2, %0;" : "+l"(d) : "l"(a), "l"(b));
}
__device__ __forceinline__ u64 fadd2(u64 a, u64 b) {
    u64 d; asm("add.rn.f32x2 %0, %1, %2;" : "=l"(d) : "l"(a), "l"(b)); return d;
}
__device__ __forceinline__ u64 pack2(float lo, float hi) {
    u64 r; asm("mov.b64 %0, {%1, %2};" : "=l"(r) : "f"(lo), "f"(hi)); return r;
}
__device__ __forceinline__ void unpack2(u64 v, float &lo, float &hi) {
    asm("mov.b64 {%0, %1}, %2;" : "=f"(lo), "=f"(hi) : "l"(v));
}

// ---------------------------------------------------------------------------
// Scratch (static device globals; no runtime allocation allowed).
// q,k,v window-partitioned: [w, h, t(49), d(32)] (w*18816 + h*1568 + t*32 + d)
// g_o unpartitioned token layout: [tok, DIM]
// ---------------------------------------------------------------------------
__device__ __align__(256) float g_q[BW*NH*L*HD];
__device__ __align__(256) float g_k[BW*NH*L*HD];
__device__ __align__(256) float g_v[BW*NH*L*HD];
__device__ __align__(256) float g_o[(size_t)TOK*DIM];

// ---------------------------------------------------------------------------
// GEMM 1: fused q / kv projection.
//   columns [0,384)    : q  = x @ q_w  + q_b, scaled by SCALE -> g_q (partitioned)
//   columns [384,768)  : k  = ctx @ kv_w[:, :384] + kv_b      -> g_k
//   columns [768,1152) : v  = ctx @ kv_w[:, 384:] + kv_b      -> g_v
// Tiles: BM=128, BN=128, BK=16, 256 threads, 8x8 per-thread micro-tile,
// packed f32x2 FMA inner product, register-staged global prefetch.
// grid = (9, 784)
// ---------------------------------------------------------------------------
__global__ __launch_bounds__(256) void gemm_qkv(
    const float* __restrict__ x, const float* __restrict__ ctx,
    const float* __restrict__ q_w, const float* __restrict__ q_b,
    const float* __restrict__ kv_w, const float* __restrict__ kv_b)
{
    __shared__ float As[16*132];   // padded row stride 132 (transposed: [k][m])
    __shared__ float Bs[16*128];   // [k][n]

    const int tid = threadIdx.x;
    const int m0  = blockIdx.y * 128;
    const int n0  = blockIdx.x * 128;

    const float* A; const float* W; const float* bias;
    float* dst; int ldw, wcol0, nl0; float scale;
    if (n0 < 384) {
        A = x;   W = q_w;  bias = q_b;  ldw = 384; wcol0 = n0;       scale = SCALE_F;
        dst = g_q; nl0 = n0;
    } else {
        A = ctx; W = kv_w; bias = kv_b; ldw = 768; wcol0 = n0 - 384; scale = 1.0f;
        if (n0 < 768) { dst = g_k; nl0 = n0 - 384; }
        else          { dst = g_v; nl0 = n0 - 768; }
    }

    const int ty = tid >> 4;   // 0..15 -> m micro-tile
    const int tx = tid & 15;   // 0..15 -> n micro-tile
    const int lm = tid >> 2;   // 0..63  (A load row)
    const int kq = tid & 3;    // A load k-quad
    const int bk = tid >> 5;   // 0..7   (B load k row)
    const int nq = tid & 31;   // B load n-quad

    u64 acc2[8][4];
#pragma unroll
    for (int i = 0; i < 8; i++)
#pragma unroll
        for (int j = 0; j < 4; j++) acc2[i][j] = 0ull;

    // prefetch first k-tile into registers
    float4 pa[2], pb[2];
#pragma unroll
    for (int it = 0; it < 2; it++) {
        pa[it] = *(const float4*)(A + (size_t)(m0 + lm + it*64) * 384 + kq * 4);
        pb[it] = *(const float4*)(W + (size_t)(bk + it*8) * ldw + wcol0 + nq * 4);
    }

    for (int k0 = 0; k0 < 384; k0 += 16) {
        // commit prefetched tile to SMEM
#pragma unroll
        for (int it = 0; it < 2; it++) {
            int m = lm + it * 64;
            As[(kq*4+0)*132 + m] = pa[it].x;
            As[(kq*4+1)*132 + m] = pa[it].y;
            As[(kq*4+2)*132 + m] = pa[it].z;
            As[(kq*4+3)*132 + m] = pa[it].w;
            *(float4*)(&Bs[(bk + it*8)*128 + nq*4]) = pb[it];
        }
        __syncthreads();
        // issue next tile's global loads (latency hidden behind compute)
        if (k0 + 16 < 384) {
#pragma unroll
            for (int it = 0; it < 2; it++) {
                pa[it] = *(const float4*)(A + (size_t)(m0 + lm + it*64) * 384 + (k0+16) + kq * 4);
                pb[it] = *(const float4*)(W + (size_t)(bk + it*8 + k0 + 16) * ldw + wcol0 + nq * 4);
            }
        }
#pragma unroll
        for (int kk = 0; kk < 16; kk++) {
            float4 a0 = *(const float4*)(&As[kk*132 + ty*8]);
            float4 a1 = *(const float4*)(&As[kk*132 + ty*8 + 4]);
            float4 b0 = *(const float4*)(&Bs[kk*128 + tx*8]);
            float4 b1 = *(const float4*)(&Bs[kk*128 + tx*8 + 4]);
            u64 bp[4] = { pack2(b0.x,b0.y), pack2(b0.z,b0.w),
                          pack2(b1.x,b1.y), pack2(b1.z,b1.w) };
            float a[8] = {a0.x,a0.y,a0.z,a0.w,a1.x,a1.y,a1.z,a1.w};
#pragma unroll
            for (int i = 0; i < 8; i++) {
                u64 ap = pack2(a[i], a[i]);
#pragma unroll
                for (int jp = 0; jp < 4; jp++)
                    ffma2(acc2[i][jp], ap, bp[jp]);
            }
        }
        __syncthreads();
    }

    // epilogue: bias, scale, scatter into partitioned layout
    float bb[8];
#pragma unroll
    for (int j = 0; j < 8; j++) bb[j] = bias[wcol0 + tx*8 + j];
    const int nl = nl0 + tx * 8;     // local col within [0,384): h = nl/32, d = nl%32
    const int hh = nl >> 5;
    const int d0 = nl & 31;          // multiple of 8 -> two float4 stores per row
#pragma unroll
    for (int i = 0; i < 8; i++) {
        float acc[8];
#pragma unroll
        for (int jp = 0; jp < 4; jp++) unpack2(acc2[i][jp], acc[jp*2], acc[jp*2+1]);
        int m = m0 + ty*8 + i;
        int b = m / 3136; int r = m - b * 3136;
        int y = r / 56;   int xx = r - y * 56;
        int w = b * 64 + (y / 7) * 8 + (xx / 7);
        int t = (y % 7) * 7 + (xx % 7);
        int base = w * 18816 + hh * 1568 + t * 32 + d0;
        float4 o0, o1;
        o0.x = (acc[0] + bb[0]) * scale; o0.y = (acc[1] + bb[1]) * scale;
        o0.z = (acc[2] + bb[2]) * scale; o0.w = (acc[3] + bb[3]) * scale;
        o1.x = (acc[4] + bb[4]) * scale; o1.y = (acc[5] + bb[5]) * scale;
        o1.z = (acc[6] + bb[6]) * scale; o1.w = (acc[7] + bb[7]) * scale;
        *(float4*)(&dst[base])     = o0;
        *(float4*)(&dst[base + 4]) = o1;
    }
}

// ---------------------------------------------------------------------------
// GEMM 2: output projection.  out = g_o @ proj_w + proj_b, row-major.
// grid = (3, 784)
// ---------------------------------------------------------------------------
__global__ __launch_bounds__(256) void gemm_proj(
    const float* __restrict__ W, const float* __restrict__ bias,
    float* __restrict__ out)
{
    __shared__ float As[16*132];
    __shared__ float Bs[16*128];

    const int tid = threadIdx.x;
    const int m0  = blockIdx.y * 128;
    const int n0  = blockIdx.x * 128;

    const int ty = tid >> 4, tx = tid & 15;
    const int lm = tid >> 2, kq = tid & 3;
    const int bk = tid >> 5, nq = tid & 31;

    u64 acc2[8][4];
#pragma unroll
    for (int i = 0; i < 8; i++)
#pragma unroll
        for (int j = 0; j < 4; j++) acc2[i][j] = 0ull;

    float4 pa[2], pb[2];
#pragma unroll
    for (int it = 0; it < 2; it++) {
        pa[it] = *(const float4*)(g_o + (size_t)(m0 + lm + it*64) * 384 + kq * 4);
        pb[it] = *(const float4*)(W + (size_t)(bk + it*8) * 384 + n0 + nq * 4);
    }

    for (int k0 = 0; k0 < 384; k0 += 16) {
#pragma unroll
        for (int it = 0; it < 2; it++) {
            int m = lm + it * 64;
            As[(kq*4+0)*132 + m] = pa[it].x;
            As[(kq*4+1)*132 + m] = pa[it].y;
            As[(kq*4+2)*132 + m] = pa[it].z;
            As[(kq*4+3)*132 + m] = pa[it].w;
            *(float4*)(&Bs[(bk + it*8)*128 + nq*4]) = pb[it];
        }
        __syncthreads();
        if (k0 + 16 < 384) {
#pragma unroll
            for (int it = 0; it < 2; it++) {
                pa[it] = *(const float4*)(g_o + (size_t)(m0 + lm + it*64) * 384 + (k0+16) + kq * 4);
                pb[it] = *(const float4*)(W + (size_t)(bk + it*8 + k0 + 16) * 384 + n0 + nq * 4);
            }
        }
#pragma unroll
        for (int kk = 0; kk < 16; kk++) {
            float4 a0 = *(const float4*)(&As[kk*132 + ty*8]);
            float4 a1 = *(const float4*)(&As[kk*132 + ty*8 + 4]);
            float4 b0 = *(const float4*)(&Bs[kk*128 + tx*8]);
            float4 b1 = *(const float4*)(&Bs[kk*128 + tx*8 + 4]);
            u64 bp[4] = { pack2(b0.x,b0.y), pack2(b0.z,b0.w),
                          pack2(b1.x,b1.y), pack2(b1.z,b1.w) };
            float a[8] = {a0.x,a0.y,a0.z,a0.w,a1.x,a1.y,a1.z,a1.w};
#pragma unroll
            for (int i = 0; i < 8; i++) {
                u64 ap = pack2(a[i], a[i]);
#pragma unroll
                for (int jp = 0; jp < 4; jp++)
                    ffma2(acc2[i][jp], ap, bp[jp]);
            }
        }
        __syncthreads();
    }

    float bb[8];
#pragma unroll
    for (int j = 0; j < 8; j++) bb[j] = bias[n0 + tx*8 + j];
#pragma unroll
    for (int i = 0; i < 8; i++) {
        float acc[8];
#pragma unroll
        for (int jp = 0; jp < 4; jp++) unpack2(acc2[i][jp], acc[jp*2], acc[jp*2+1]);
        int m = m0 + ty*8 + i;
        float4 o0, o1;
        o0.x = acc[0] + bb[0]; o0.y = acc[1] + bb[1];
        o0.z = acc[2] + bb[2]; o0.w = acc[3] + bb[3];
        o1.x = acc[4] + bb[4]; o1.y = acc[5] + bb[5];
        o1.z = acc[6] + bb[6]; o1.w = acc[7] + bb[7];
        *(float4*)(&out[(size_t)m * 384 + n0 + tx*8])     = o0;
        *(float4*)(&out[(size_t)m * 384 + n0 + tx*8 + 4]) = o1;
    }
}

// ---------------------------------------------------------------------------
// Attention: one block per (window, head). 256 threads = 8 warps.
// Warp-row fused score+softmax (dual accumulator chains), per-warp AV.
// Single block-wide barrier (after tile loads).
// ---------------------------------------------------------------------------
#define ATTN_SMEM_FLOATS (3*49*36 + 3*169*36 + 49*50)   // 25994
#define ATTN_SMEM_BYTES  (ATTN_SMEM_FLOATS*4 + 2408)    // 106384

__global__ __launch_bounds__(256) void attn_kernel(const float* __restrict__ rpe_table)
{
    extern __shared__ float sm[];
    float* SQ = sm;
    float* SK = SQ + 49*36;
    float* SV = SK + 49*36;
    float* TQ = SV + 49*36;
    float* TK = TQ + 169*36;
    float* TV = TK + 169*36;
    float* SP = TV + 169*36;
    unsigned char* IDX = (unsigned char*)(SP + 49*50);

    const int tid = threadIdx.x;
    const int wh  = blockIdx.x;      // w*12 + h (matches g_q layout)
    const int h   = wh % 12;
    const int w   = wh / 12;

    const float4* gq = (const float4*)(g_q + (size_t)wh * 1568);
    const float4* gk = (const float4*)(g_k + (size_t)wh * 1568);
    const float4* gv = (const float4*)(g_v + (size_t)wh * 1568);
    for (int u = tid; u < 392; u += 256) {
        int r = u >> 3, c = u & 7;
        *(float4*)(&SQ[r*36 + c*4]) = gq[u];
        *(float4*)(&SK[r*36 + c*4]) = gk[u];
        *(float4*)(&SV[r*36 + c*4]) = gv[u];
    }
    const float* tbp = rpe_table + h * 96;
    for (int u = tid; u < 169*8; u += 256) {
        int r = u >> 3, c = u & 7;
        const float* row = tbp + (size_t)r * 1152;
        float4 a  = *(const float4*)(row + c*4);        // q_rpe
        float4 b  = *(const float4*)(row + 32 + c*4);   // k_rpe
        float4 cv = *(const float4*)(row + 64 + c*4);   // v_rpe
        a.x *= SCALE_F; a.y *= SCALE_F; a.z *= SCALE_F; a.w *= SCALE_F;
        *(float4*)(&TQ[r*36 + c*4]) = a;
        *(float4*)(&TK[r*36 + c*4]) = b;
        *(float4*)(&TV[r*36 + c*4]) = cv;
    }
    for (int p = tid; p < 2401; p += 256) {
        int i = p / 49, j = p - i * 49;
        int yi = i / 7, xi = i - yi * 7;
        int yj = j / 7, xj = j - yj * 7;
        IDX[p] = (unsigned char)((yi - yj + 6) * 13 + (xi - xj + 6));
    }
    __syncthreads();   // the only block-wide barrier

    const int lane = tid & 31, wrp = tid >> 5;

    for (int i = wrp; i < 49; i += 8) {
        u64 qp[16];
#pragma unroll
        for (int c = 0; c < 8; c++) {
            float4 q = *(const float4*)(&SQ[i*36 + c*4]);
            qp[c*2]   = pack2(q.x, q.y);
            qp[c*2+1] = pack2(q.z, q.w);
        }
        const unsigned char* ir = IDX + i * 49;

        float x0;
        {
            int j = lane, id = ir[j];
            const float4* k4  = (const float4*)(SK + j  * 36);
            const float4* qr4 = (const float4*)(TQ + id * 36);
            const float4* kr4 = (const float4*)(TK + id * 36);
            u64 accA = 0ull, accB = 0ull;
#pragma unroll
            for (int c = 0; c < 8; c++) {
                float4 k = k4[c], qr = qr4[c], kr = kr4[c];
                u64 k01 = pack2(k.x,k.y), k23 = pack2(k.z,k.w);
                ffma2(accA, qp[c*2],   fadd2(k01, pack2(kr.x,kr.y)));
                ffma2(accB, k01, pack2(qr.x,qr.y));
                ffma2(accA, qp[c*2+1], fadd2(k23, pack2(kr.z,kr.w)));
                ffma2(accB, k23, pack2(qr.z,qr.w));
            }
            u64 acc = fadd2(accA, accB);
            float lo, hi; unpack2(acc, lo, hi); x0 = lo + hi;
        }
        float x1 = -FLT_MAX;
        if (lane < 17) {
            int j = lane + 32, id = ir[j];
            const float4* k4  = (const float4*)(SK + j  * 36);
            const float4* qr4 = (const float4*)(TQ + id * 36);
            const float4* kr4 = (const float4*)(TK + id * 36);
            u64 accA = 0ull, accB = 0ull;
#pragma unroll
            for (int c = 0; c < 8; c++) {
                float4 k = k4[c], qr = qr4[c], kr = kr4[c];
                u64 k01 = pack2(k.x,k.y), k23 = pack2(k.z,k.w);
                ffma2(accA, qp[c*2],   fadd2(k01, pack2(kr.x,kr.y)));
                ffma2(accB, k01, pack2(qr.x,qr.y));
                ffma2(accA, qp[c*2+1], fadd2(k23, pack2(kr.z,kr.w)));
                ffma2(accB, k23, pack2(qr.z,qr.w));
            }
            u64 acc = fadd2(accA, accB);
            float lo, hi; unpack2(acc, lo, hi); x1 = lo + hi;
        }

        float mx = fmaxf(x0, x1);
#pragma unroll
        for (int o = 16; o > 0; o >>= 1) mx = fmaxf(mx, __shfl_xor_sync(0xffffffffu, mx, o));
        float e0 = __expf(x0 - mx);
        float e1 = (lane < 17) ? __expf(x1 - mx) : 0.f;
        float s = e0 + e1;
#pragma unroll
        for (int o = 16; o > 0; o >>= 1) s += __shfl_xor_sync(0xffffffffu, s, o);
        float inv = 1.0f / s;
        SP[i*50 + lane] = e0 * inv;
        if (lane < 17) SP[i*50 + 32 + lane] = e1 * inv;
    }
    __syncwarp();

    const int b = w >> 6, win = w & 63, wy = win >> 3, wx = win & 7;
    const int cq = lane & 7;
#pragma unroll
    for (int pass = 0; pass < 2; pass++) {
        int i = wrp + (pass * 4 + (lane >> 3)) * 8;
        if (i >= 49) continue;
        const float* pr = SP + i * 50;
        const unsigned char* ir = IDX + i * 49;
        u64 acc01 = 0ull, acc23 = 0ull;
        for (int j = 0; j < 49; j++) {
            float pw = pr[j];
            int id = ir[j];
            float4 vv = *(const float4*)(&SV[j  * 36 + cq * 4]);
            float4 vr = *(const float4*)(&TV[id * 36 + cq * 4]);
            u64 pw2 = pack2(pw, pw);
            ffma2(acc01, pw2, fadd2(pack2(vv.x,vv.y), pack2(vr.x,vr.y)));
            ffma2(acc23, pw2, fadd2(pack2(vv.z,vv.w), pack2(vr.z,vr.w)));
        }
        float4 acc;
        unpack2(acc01, acc.x, acc.y);
        unpack2(acc23, acc.z, acc.w);
        int ys = i / 7, xs = i - ys * 7;
        int tok = b * 3136 + (wy * 7 + ys) * 56 + (wx * 7 + xs);
        *(float4*)(&g_o[(size_t)tok * 384 + h * 32 + cq * 4]) = acc;
    }
}

// ---------------------------------------------------------------------------
// Launch
// ---------------------------------------------------------------------------
extern "C" void kernel_launch(void* const* d_in, const int* in_sizes, int n_in,
                              void* d_out, int out_size)
{
    const float* x      = (const float*)d_in[0];
    const float* ctx    = (const float*)d_in[1];
    const float* rpe    = (const float*)d_in[2];
    const float* q_w    = (const float*)d_in[3];
    const float* q_b    = (const float*)d_in[4];
    const float* kv_w   = (const float*)d_in[5];
    const float* kv_b   = (const float*)d_in[6];
    const float* proj_w = (const float*)d_in[7];
    const float* proj_b = (const float*)d_in[8];
    float* out = (float*)d_out;

    cudaFuncSetAttribute(attn_kernel, cudaFuncAttributeMaxDynamicSharedMemorySize,
                         ATTN_SMEM_BYTES);

    gemm_qkv<<<dim3(9, 784), 256>>>(x, ctx, q_w, q_b, kv_w, kv_b);
    attn_kernel<<<BW * NH, 256, ATTN_SMEM_BYTES>>>(rpe);
    gemm_proj<<<dim3(3, 784), 256>>>(proj_w, proj_b, out);
}

// round 16
// speedup vs baseline: 1.3236x; 1.3236x over previous
#include <cuda_runtime.h>
#include <cuda_bf16.h>
#include <math.h>
#include <float.h>
#include <stdint.h>

// ---------------------------------------------------------------------------
// Problem constants
// ---------------------------------------------------------------------------
#define BATCH   32
#define HW      56
#define DIM     384
#define NH      12
#define HD      32
#define WS      7
#define L       49
#define NWIN    64
#define BW      (BATCH*NWIN)        // 2048 windows
#define TOK     (BATCH*HW*HW)       // 100352 tokens
#define SCALE_F 0.17677669529663687f

typedef unsigned long long u64;

// ---------------------------------------------------------------------------
// Packed fp32x2 helpers (attention kernel)
// ---------------------------------------------------------------------------
__device__ __forceinline__ void ffma2(u64 &d, u64 a, u64 b) {
    asm("fma.rn.f32x2 %0, %1, %2, %0;" : "+l"(d) : "l"(a), "l"(b));
}
__device__ __forceinline__ u64 fadd2(u64 a, u64 b) {
    u64 d; asm("add.rn.f32x2 %0, %1, %2;" : "=l"(d) : "l"(a), "l"(b)); return d;
}
__device__ __forceinline__ u64 pack2(float lo, float hi) {
    u64 r; asm("mov.b64 %0, {%1, %2};" : "=l"(r) : "f"(lo), "f"(hi)); return r;
}
__device__ __forceinline__ void unpack2(u64 v, float &lo, float &hi) {
    asm("mov.b64 {%0, %1}, %2;" : "=f"(lo), "=f"(hi) : "l"(v));
}

// ---------------------------------------------------------------------------
// Scratch (static device globals; referenced ONLY from device code).
// q,k,v window-partitioned: [w, h, t(49), d(32)]; g_o token layout [tok, DIM]
// ---------------------------------------------------------------------------
__device__ __align__(256) float g_q[BW*NH*L*HD];
__device__ __align__(256) float g_k[BW*NH*L*HD];
__device__ __align__(256) float g_v[BW*NH*L*HD];
__device__ __align__(256) float g_o[(size_t)TOK*DIM];
// transposed + bf16-split weights: rows 0..383 q_w^T, 384..1151 kv_w^T, 1152..1535 proj_w^T
__device__ __align__(256) __nv_bfloat16 g_wth[1536*384];
__device__ __align__(256) __nv_bfloat16 g_wtl[1536*384];

// ---------------------------------------------------------------------------
// mma.sync / ldmatrix helpers (sm_80-era; valid on plain sm_103)
// ---------------------------------------------------------------------------
__device__ __forceinline__ uint32_t smem_u32(const void* p) {
    uint32_t a;
    asm("{ .reg .u64 t; cvta.to.shared.u64 t, %1; cvt.u32.u64 %0, t; }" : "=r"(a) : "l"(p));
    return a;
}
__device__ __forceinline__ void ldsm4(uint32_t* r, uint32_t addr) {
    asm volatile("ldmatrix.sync.aligned.m8n8.x4.shared.b16 {%0,%1,%2,%3}, [%4];"
        : "=r"(r[0]), "=r"(r[1]), "=r"(r[2]), "=r"(r[3]) : "r"(addr));
}
__device__ __forceinline__ void mma_bf16(float* c, const uint32_t* a, uint32_t b0, uint32_t b1) {
    asm volatile(
        "mma.sync.aligned.m16n8k16.row.col.f32.bf16.bf16.f32 "
        "{%0,%1,%2,%3}, {%4,%5,%6,%7}, {%8,%9}, {%0,%1,%2,%3};"
        : "+f"(c[0]), "+f"(c[1]), "+f"(c[2]), "+f"(c[3])
        : "r"(a[0]), "r"(a[1]), "r"(a[2]), "r"(a[3]), "r"(b0), "r"(b1));
}
// split 16 fp32 -> 8 packed bf16x2 hi + 8 lo
__device__ __forceinline__ void cvt16(const float4* pa, uint32_t* hi, uint32_t* lo) {
    const float* v = (const float*)pa;
#pragma unroll
    for (int p = 0; p < 8; p++) {
        __nv_bfloat162 h = __floats2bfloat162_rn(v[2*p], v[2*p+1]);
        float2 hf = __bfloat1622float2(h);
        __nv_bfloat162 l = __floats2bfloat162_rn(v[2*p] - hf.x, v[2*p+1] - hf.y);
        hi[p] = *(uint32_t*)&h;
        lo[p] = *(uint32_t*)&l;
    }
}

// ---------------------------------------------------------------------------
// prep_w: transpose + bf16-split weights into g_wth/g_wtl via SMEM 32x32
// tiles (both global sides coalesced). grid = (12, 48), 256 threads.
// ---------------------------------------------------------------------------
__global__ __launch_bounds__(256) void prep_w(
    const float* __restrict__ qw, const float* __restrict__ kvw,
    const float* __restrict__ pw)
{
    __shared__ float tile[32][33];
    const int tx = threadIdx.x & 31, ty = threadIdx.x >> 5;   // 32 x 8
    const int kk0 = blockIdx.x * 32, nt0 = blockIdx.y * 32;

    const float* src; int ld, c0;
    if (nt0 < 384)       { src = qw;  ld = 384; c0 = nt0; }
    else if (nt0 < 1152) { src = kvw; ld = 768; c0 = nt0 - 384; }
    else                 { src = pw;  ld = 384; c0 = nt0 - 1152; }

#pragma unroll
    for (int i = 0; i < 4; i++)
        tile[ty + i * 8][tx] = src[(size_t)(kk0 + ty + i * 8) * ld + c0 + tx];
    __syncthreads();

#pragma unroll
    for (int i = 0; i < 4; i++) {
        float v = tile[tx][ty + i * 8];
        __nv_bfloat16 h = __float2bfloat16_rn(v);
        size_t e = (size_t)(nt0 + ty + i * 8) * 384 + kk0 + tx;
        g_wth[e] = h;
        g_wtl[e] = __float2bfloat16_rn(v - __bfloat162float(h));
    }
}

// ---------------------------------------------------------------------------
// gemm_mma: C[128 x 128] tile = A[128 x 384] (fp32) @ Wt^T (bf16 hi/lo)
// via mma.sync m16n8k16 bf16, 3-pass hi/lo split (AhBh + AlBh + AhBl).
// is_proj==0: grid (9, 784). blockIdx.x -> global col gn = bx*128 in
//   [0,1152): sec = gn/384 selects {x->g_q (scaled), ctx->g_k, ctx->g_v},
//   window-partitioned scatter.
// is_proj==1: grid (3, 784). A = g_o, weights rows 1152+, dst = dout
//   row-major.
// 8 warps: wm = wid&1 (m 64), wn = wid>>1 (n 32). 12 chunks of BK=32,
// double-buffered SMEM (A conv in-kernel, B via cp.async).
// SMEM rows padded to 40 bf16 (80B -> conflict-free ldmatrix).
// ---------------------------------------------------------------------------
#define SA(b)   ((b)*20480)            // hi at +0 (10240B), lo at +10240
#define SB(b)   (40960 + (b)*20480)    // hi at +0, lo at +10240
#define GEMM_SMEM 81920

__global__ __launch_bounds__(256) void gemm_mma(
    const float* __restrict__ x, const float* __restrict__ ctx,
    const float* __restrict__ q_b, const float* __restrict__ kv_b,
    const float* __restrict__ proj_b, float* __restrict__ dout,
    int is_proj)
{
    extern __shared__ char smem[];
    const uint32_t sb = smem_u32(smem);
    const int tid = threadIdx.x, lane = tid & 31, wid = tid >> 5;
    const int wm = wid & 1, wn = wid >> 1;
    const int m0 = blockIdx.y * 128;
    const int gn = blockIdx.x * 128;

    // per-CTA section resolution (all device-global refs stay in device code)
    const float* A; const float* biasp; float scale; float* dst; int wtrow; int mode;
    if (is_proj) {
        A = g_o; biasp = proj_b + gn; scale = 1.0f; dst = dout;
        wtrow = 1152 + gn; mode = 1;
    } else {
        int sec = gn / 384;                  // 0: q, 1: k, 2: v
        A      = sec ? ctx : x;
        biasp  = sec ? (kv_b + (gn - 384)) : (q_b + gn);
        scale  = sec ? 1.0f : SCALE_F;
        dst    = (sec == 0) ? g_q : ((sec == 1) ? g_k : g_v);
        wtrow  = gn; mode = 0;
    }
    const int hl = (is_proj ? gn : (gn % 384)) + wn * 32;  // col base of warp
    const int h  = (gn % 384 + wn * 32) >> 5;              // head (mode 0)

    const int arow_ld = tid >> 1, ahalf = tid & 1;       // A loader mapping
    const int brow_ld = tid & 127, bhalf = tid >> 7;     // B loader mapping

    // ---- loaders ----
    auto loadB_async = [&](int kc, int b) {
        uint32_t d0 = sb + SB(b) + (uint32_t)(brow_ld * 80 + bhalf * 32);
        const __nv_bfloat16* sh = g_wth + (size_t)(wtrow + brow_ld) * 384 + kc * 32 + bhalf * 16;
        const __nv_bfloat16* sl = g_wtl + (size_t)(wtrow + brow_ld) * 384 + kc * 32 + bhalf * 16;
        asm volatile("cp.async.cg.shared.global [%0], [%1], 16;" :: "r"(d0),          "l"(sh)     : "memory");
        asm volatile("cp.async.cg.shared.global [%0], [%1], 16;" :: "r"(d0 + 16),     "l"(sh + 8) : "memory");
        asm volatile("cp.async.cg.shared.global [%0], [%1], 16;" :: "r"(d0 + 10240),  "l"(sl)     : "memory");
        asm volatile("cp.async.cg.shared.global [%0], [%1], 16;" :: "r"(d0 + 10256),  "l"(sl + 8) : "memory");
        asm volatile("cp.async.commit_group;" ::: "memory");
    };
    auto ldgA = [&](int kc, float4* pa) {
        const float* ap = A + (size_t)(m0 + arow_ld) * 384 + kc * 32 + ahalf * 16;
#pragma unroll
        for (int i = 0; i < 4; i++) pa[i] = ((const float4*)ap)[i];
    };
    auto stsA = [&](const float4* pa, int b) {
        uint32_t hi[8], lo[8];
        cvt16(pa, hi, lo);
        char* d = smem + SA(b) + arow_ld * 80 + ahalf * 32;
        *(uint4*)(d)              = *(uint4*)(hi);
        *(uint4*)(d + 16)         = *(uint4*)(hi + 4);
        *(uint4*)(d + 10240)      = *(uint4*)(lo);
        *(uint4*)(d + 10240 + 16) = *(uint4*)(lo + 4);
    };

    // ---- prologue: chunk 0 ----
    {
        float4 pa[4];
        ldgA(0, pa);
        loadB_async(0, 0);
        stsA(pa, 0);
        asm volatile("cp.async.wait_group 0;" ::: "memory");
    }
    __syncthreads();

    float acc[4][4][4];
#pragma unroll
    for (int i = 0; i < 4; i++)
#pragma unroll
        for (int j = 0; j < 4; j++)
#pragma unroll
            for (int c = 0; c < 4; c++) acc[i][j][c] = 0.f;

    // ---- main loop: 12 chunks of BK=32 ----
    for (int kc = 0; kc < 12; kc++) {
        const int bb = kc & 1;
        float4 pa[4];
        if (kc < 11) {
            loadB_async(kc + 1, (kc + 1) & 1);
            ldgA(kc + 1, pa);
        }

        // canonical ldmatrix addressing: (lane%16)*ld + (lane/16)*16B
        const uint32_t lrow = (uint32_t)(lane & 15) * 80 + (uint32_t)(lane >> 4) * 16;
#pragma unroll
        for (int ks = 0; ks < 2; ks++) {
            uint32_t ah[4][4], al[4][4];
            uint32_t aBase = sb + SA(bb) + (uint32_t)(wm * 64) * 80 + (uint32_t)ks * 32 + lrow;
#pragma unroll
            for (int mi = 0; mi < 4; mi++) {
                ldsm4(ah[mi], aBase + mi * 1280);
                ldsm4(al[mi], aBase + mi * 1280 + 10240);
            }
            uint32_t bBase = sb + SB(bb) + (uint32_t)(wn * 32) * 80 + (uint32_t)ks * 32 + lrow;
#pragma unroll
            for (int bq = 0; bq < 2; bq++) {
                uint32_t bh[4], bl[4];
                ldsm4(bh, bBase + bq * 1280);
                ldsm4(bl, bBase + bq * 1280 + 10240);
                // frag nj=2bq: {r0,r2}; nj=2bq+1: {r1,r3}
#pragma unroll
                for (int mi = 0; mi < 4; mi++) {
                    mma_bf16(acc[mi][2*bq],   ah[mi], bh[0], bh[2]);
                    mma_bf16(acc[mi][2*bq],   al[mi], bh[0], bh[2]);
                    mma_bf16(acc[mi][2*bq],   ah[mi], bl[0], bl[2]);
                    mma_bf16(acc[mi][2*bq+1], ah[mi], bh[1], bh[3]);
                    mma_bf16(acc[mi][2*bq+1], al[mi], bh[1], bh[3]);
                    mma_bf16(acc[mi][2*bq+1], ah[mi], bl[1], bl[3]);
                }
            }
        }

        if (kc < 11) stsA(pa, (kc + 1) & 1);
        asm volatile("cp.async.wait_group 0;" ::: "memory");
        __syncthreads();
    }

    // ---- epilogue ----
    const int tr = lane >> 2, tc = (lane & 3) * 2;
    float b0v[4], b1v[4];
#pragma unroll
    for (int nj = 0; nj < 4; nj++) {
        b0v[nj] = biasp[wn * 32 + nj * 8 + tc];
        b1v[nj] = biasp[wn * 32 + nj * 8 + tc + 1];
    }

#pragma unroll
    for (int mi = 0; mi < 4; mi++) {
#pragma unroll
        for (int sub = 0; sub < 2; sub++) {
            int m = m0 + wm * 64 + mi * 16 + tr + sub * 8;
            float* base;
            if (mode == 0) {
                int bI = m / 3136, rI = m - bI * 3136;
                int yI = rI / 56, xI = rI - yI * 56;
                int w  = bI * 64 + (yI / 7) * 8 + (xI / 7);
                int t  = (yI % 7) * 7 + (xI % 7);
                base = dst + ((size_t)w * 18816 + (size_t)h * 1568 + t * 32);
            } else {
                base = dst + (size_t)m * 384 + hl;
            }
#pragma unroll
            for (int nj = 0; nj < 4; nj++) {
                float2 o;
                o.x = (acc[mi][nj][sub*2]   + b0v[nj]) * scale;
                o.y = (acc[mi][nj][sub*2+1] + b1v[nj]) * scale;
                *(float2*)(base + nj * 8 + tc) = o;
            }
        }
    }
}

// ---------------------------------------------------------------------------
// Attention: one block per (window, head). 256 threads = 8 warps.
// Warp-row fused score+softmax (dual accumulator chains), per-warp AV.
// (unchanged from the passing round-11 kernel)
// ---------------------------------------------------------------------------
#define ATTN_SMEM_FLOATS (3*49*36 + 3*169*36 + 49*50)   // 25994
#define ATTN_SMEM_BYTES  (ATTN_SMEM_FLOATS*4 + 2408)    // 106384

__global__ __launch_bounds__(256) void attn_kernel(const float* __restrict__ rpe_table)
{
    extern __shared__ float sm[];
    float* SQ = sm;
    float* SK = SQ + 49*36;
    float* SV = SK + 49*36;
    float* TQ = SV + 49*36;
    float* TK = TQ + 169*36;
    float* TV = TK + 169*36;
    float* SP = TV + 169*36;
    unsigned char* IDX = (unsigned char*)(SP + 49*50);

    const int tid = threadIdx.x;
    const int wh  = blockIdx.x;
    const int h   = wh % 12;
    const int w   = wh / 12;

    const float4* gq = (const float4*)(g_q + (size_t)wh * 1568);
    const float4* gk = (const float4*)(g_k + (size_t)wh * 1568);
    const float4* gv = (const float4*)(g_v + (size_t)wh * 1568);
    for (int u = tid; u < 392; u += 256) {
        int r = u >> 3, c = u & 7;
        *(float4*)(&SQ[r*36 + c*4]) = gq[u];
        *(float4*)(&SK[r*36 + c*4]) = gk[u];
        *(float4*)(&SV[r*36 + c*4]) = gv[u];
    }
    const float* tbp = rpe_table + h * 96;
    for (int u = tid; u < 169*8; u += 256) {
        int r = u >> 3, c = u & 7;
        const float* row = tbp + (size_t)r * 1152;
        float4 a  = *(const float4*)(row + c*4);
        float4 b  = *(const float4*)(row + 32 + c*4);
        float4 cv = *(const float4*)(row + 64 + c*4);
        a.x *= SCALE_F; a.y *= SCALE_F; a.z *= SCALE_F; a.w *= SCALE_F;
        *(float4*)(&TQ[r*36 + c*4]) = a;
        *(float4*)(&TK[r*36 + c*4]) = b;
        *(float4*)(&TV[r*36 + c*4]) = cv;
    }
    for (int p = tid; p < 2401; p += 256) {
        int i = p / 49, j = p - i * 49;
        int yi = i / 7, xi = i - yi * 7;
        int yj = j / 7, xj = j - yj * 7;
        IDX[p] = (unsigned char)((yi - yj + 6) * 13 + (xi - xj + 6));
    }
    __syncthreads();

    const int lane = tid & 31, wrp = tid >> 5;

    for (int i = wrp; i < 49; i += 8) {
        u64 qp[16];
#pragma unroll
        for (int c = 0; c < 8; c++) {
            float4 q = *(const float4*)(&SQ[i*36 + c*4]);
            qp[c*2]   = pack2(q.x, q.y);
            qp[c*2+1] = pack2(q.z, q.w);
        }
        const unsigned char* ir = IDX + i * 49;

        float x0;
        {
            int j = lane, id = ir[j];
            const float4* k4  = (const float4*)(SK + j  * 36);
            const float4* qr4 = (const float4*)(TQ + id * 36);
            const float4* kr4 = (const float4*)(TK + id * 36);
            u64 accA = 0ull, accB = 0ull;
#pragma unroll
            for (int c = 0; c < 8; c++) {
                float4 k = k4[c], qr = qr4[c], kr = kr4[c];
                u64 k01 = pack2(k.x,k.y), k23 = pack2(k.z,k.w);
                ffma2(accA, qp[c*2],   fadd2(k01, pack2(kr.x,kr.y)));
                ffma2(accB, k01, pack2(qr.x,qr.y));
                ffma2(accA, qp[c*2+1], fadd2(k23, pack2(kr.z,kr.w)));
                ffma2(accB, k23, pack2(qr.z,qr.w));
            }
            u64 acc = fadd2(accA, accB);
            float lo, hi; unpack2(acc, lo, hi); x0 = lo + hi;
        }
        float x1 = -FLT_MAX;
        if (lane < 17) {
            int j = lane + 32, id = ir[j];
            const float4* k4  = (const float4*)(SK + j  * 36);
            const float4* qr4 = (const float4*)(TQ + id * 36);
            const float4* kr4 = (const float4*)(TK + id * 36);
            u64 accA = 0ull, accB = 0ull;
#pragma unroll
            for (int c = 0; c < 8; c++) {
                float4 k = k4[c], qr = qr4[c], kr = kr4[c];
                u64 k01 = pack2(k.x,k.y), k23 = pack2(k.z,k.w);
                ffma2(accA, qp[c*2],   fadd2(k01, pack2(kr.x,kr.y)));
                ffma2(accB, k01, pack2(qr.x,qr.y));
                ffma2(accA, qp[c*2+1], fadd2(k23, pack2(kr.z,kr.w)));
                ffma2(accB, k23, pack2(qr.z,qr.w));
            }
            u64 acc = fadd2(accA, accB);
            float lo, hi; unpack2(acc, lo, hi); x1 = lo + hi;
        }

        float mx = fmaxf(x0, x1);
#pragma unroll
        for (int o = 16; o > 0; o >>= 1) mx = fmaxf(mx, __shfl_xor_sync(0xffffffffu, mx, o));
        float e0 = __expf(x0 - mx);
        float e1 = (lane < 17) ? __expf(x1 - mx) : 0.f;
        float s = e0 + e1;
#pragma unroll
        for (int o = 16; o > 0; o >>= 1) s += __shfl_xor_sync(0xffffffffu, s, o);
        float inv = 1.0f / s;
        SP[i*50 + lane] = e0 * inv;
        if (lane < 17) SP[i*50 + 32 + lane] = e1 * inv;
    }
    __syncwarp();

    const int b = w >> 6, win = w & 63, wy = win >> 3, wx = win & 7;
    const int cq = lane & 7;
#pragma unroll
    for (int pass = 0; pass < 2; pass++) {
        int i = wrp + (pass * 4 + (lane >> 3)) * 8;
        if (i >= 49) continue;
        const float* pr = SP + i * 50;
        const unsigned char* ir = IDX + i * 49;
        u64 acc01 = 0ull, acc23 = 0ull;
        for (int j = 0; j < 49; j++) {
            float pw = pr[j];
            int id = ir[j];
            float4 vv = *(const float4*)(&SV[j  * 36 + cq * 4]);
            float4 vr = *(const float4*)(&TV[id * 36 + cq * 4]);
            u64 pw2 = pack2(pw, pw);
            ffma2(acc01, pw2, fadd2(pack2(vv.x,vv.y), pack2(vr.x,vr.y)));
            ffma2(acc23, pw2, fadd2(pack2(vv.z,vv.w), pack2(vr.z,vr.w)));
        }
        float4 acc;
        unpack2(acc01, acc.x, acc.y);
        unpack2(acc23, acc.z, acc.w);
        int ys = i / 7, xs = i - ys * 7;
        int tok = b * 3136 + (wy * 7 + ys) * 56 + (wx * 7 + xs);
        *(float4*)(&g_o[(size_t)tok * 384 + h * 32 + cq * 4]) = acc;
    }
}

// ---------------------------------------------------------------------------
// Launch — only harness-provided pointers cross the launch boundary.
// ---------------------------------------------------------------------------
extern "C" void kernel_launch(void* const* d_in, const int* in_sizes, int n_in,
                              void* d_out, int out_size)
{
    const float* x      = (const float*)d_in[0];
    const float* ctx    = (const float*)d_in[1];
    const float* rpe    = (const float*)d_in[2];
    const float* q_w    = (const float*)d_in[3];
    const float* q_b    = (const float*)d_in[4];
    const float* kv_w   = (const float*)d_in[5];
    const float* kv_b   = (const float*)d_in[6];
    const float* proj_w = (const float*)d_in[7];
    const float* proj_b = (const float*)d_in[8];
    float* out = (float*)d_out;

    cudaFuncSetAttribute(attn_kernel, cudaFuncAttributeMaxDynamicSharedMemorySize,
                         ATTN_SMEM_BYTES);
    cudaFuncSetAttribute(gemm_mma, cudaFuncAttributeMaxDynamicSharedMemorySize,
                         GEMM_SMEM);

    prep_w<<<dim3(12, 48), 256>>>(q_w, kv_w, proj_w);
    gemm_mma<<<dim3(9, 784), 256, GEMM_SMEM>>>(x, ctx, q_b, kv_b, proj_b, nullptr, 0);
    attn_kernel<<<BW * NH, 256, ATTN_SMEM_BYTES>>>(rpe);
    gemm_mma<<<dim3(3, 784), 256, GEMM_SMEM>>>(x, ctx, q_b, kv_b, proj_b, out, 1);
}